// round 15
// baseline (speedup 1.0000x reference)
#include <cuda_runtime.h>
#include <cuda_fp16.h>
#include <cstdint>

#define N_TOK 16384
#define DDIM  1024
#define NEXP  8

#define BM 128
#define BN 128
#define BK 64
#define NCHUNK (DDIM / BK)       // 16
#define GT 256                   // 8 warps

#define LO_SCALE 1024.0f
#define LO_INV   (1.0f / 1024.0f)

// ---- shared memory layout ----
// fp16 tiles (double buffered): rows padded to 72 halves (144 B).
// 3 tiles per stage: A_hi, A_lo(x1024), B_hi.
#define ROWB   144
#define MATB   (BM * ROWB)                // 18432 B per matrix tile
#define STAGEB (3 * MATB)                 // 55296 B per stage
#define OFF_AHI 0
#define OFF_ALO (1 * MATB)
#define OFF_BHI (2 * MATB)
#define SM_SROW 0
#define SM_BF   512
#define SMEM_TOTAL (SM_BF + 2 * STAGEB)   // 111104 B

// ---------------------------------------------------------------------------
// Device scratch: ONLY the small routing tables.
// ---------------------------------------------------------------------------
__device__ int g_cnt[NEXP];
__device__ int g_idx[NEXP * N_TOK];

// ---------------------------------------------------------------------------
// PTX helpers (sm_80-level only)
// ---------------------------------------------------------------------------
__device__ __forceinline__ uint32_t smem_u32(const void* p) {
    uint32_t a;
    asm("{ .reg .u64 t; cvta.to.shared.u64 t, %1; cvt.u32.u64 %0, t; }"
        : "=r"(a) : "l"(p));
    return a;
}
__device__ __forceinline__ void ldsm4(uint32_t& r0, uint32_t& r1,
                                      uint32_t& r2, uint32_t& r3, uint32_t a) {
    asm volatile("ldmatrix.sync.aligned.m8n8.x4.shared.b16 {%0,%1,%2,%3}, [%4];"
                 : "=r"(r0), "=r"(r1), "=r"(r2), "=r"(r3) : "r"(a));
}
// fp16 MMA, f32 accumulate (hi term).
__device__ __forceinline__ void mma16816(float* d, const uint32_t* a,
                                         const uint32_t* b) {
    asm("mma.sync.aligned.m16n8k16.row.col.f32.f16.f16.f32 "
        "{%0,%1,%2,%3}, {%4,%5,%6,%7}, {%8,%9}, {%0,%1,%2,%3};"
        : "+f"(d[0]), "+f"(d[1]), "+f"(d[2]), "+f"(d[3])
        : "r"(a[0]), "r"(a[1]), "r"(a[2]), "r"(a[3]),
          "r"(b[0]), "r"(b[1]));
}
// fp16 MMA, f16 accumulate (lo term) — D/C are 2x f16x2 regs:
// d[0] = {c0,c1}, d[1] = {c2,c3}, same element positions as the f32 form.
__device__ __forceinline__ void mma16816_h(uint32_t* d, const uint32_t* a,
                                           const uint32_t* b) {
    asm("mma.sync.aligned.m16n8k16.row.col.f16.f16.f16.f16 "
        "{%0,%1}, {%2,%3,%4,%5}, {%6,%7}, {%0,%1};"
        : "+r"(d[0]), "+r"(d[1])
        : "r"(a[0]), "r"(a[1]), "r"(a[2]), "r"(a[3]),
          "r"(b[0]), "r"(b[1]));
}
// fp16 split: hi = f16x2(f0,f1), lo = f16x2 of residuals * LO_SCALE.
__device__ __forceinline__ void pack_split_f16(float f0, float f1,
                                               uint32_t& hi, uint32_t& lo) {
    __half2 h = __floats2half2_rn(f0, f1);
    float2 hf = __half22float2(h);
    __half2 l = __floats2half2_rn((f0 - hf.x) * LO_SCALE,
                                  (f1 - hf.y) * LO_SCALE);
    hi = *reinterpret_cast<uint32_t*>(&h);
    lo = *reinterpret_cast<uint32_t*>(&l);
}
__device__ __forceinline__ uint32_t pack_f16(float f0, float f1) {
    __half2 h = __floats2half2_rn(f0, f1);
    return *reinterpret_cast<uint32_t*>(&h);
}
__device__ __forceinline__ void sts2(uint32_t a, uint32_t v0, uint32_t v1) {
    asm volatile("st.shared.v2.u32 [%0], {%1,%2};" :: "r"(a), "r"(v0), "r"(v1));
}

// ---------------------------------------------------------------------------
// Kernel 0: zero per-expert counters (graph replays need this every launch).
// ---------------------------------------------------------------------------
__global__ void zero_cnt_kernel() {
    if (threadIdx.x < NEXP) g_cnt[threadIdx.x] = 0;
}

// ---------------------------------------------------------------------------
// Kernel 1: router. One warp/token; argmax, first-index tie-break.
// ---------------------------------------------------------------------------
__global__ void router_kernel(const float* __restrict__ x,
                              const float* __restrict__ rw,
                              const float* __restrict__ rb) {
    int gwarp = (int)((blockIdx.x * blockDim.x + threadIdx.x) >> 5);
    int lane  = threadIdx.x & 31;
    if (gwarp >= N_TOK) return;
    const float* xr = x + (size_t)gwarp * DDIM;
    float acc[NEXP];
#pragma unroll
    for (int e = 0; e < NEXP; e++) acc[e] = 0.f;
    for (int k = lane; k < DDIM; k += 32) {
        float xv = __ldg(xr + k);
#pragma unroll
        for (int e = 0; e < NEXP; e++)
            acc[e] = fmaf(xv, __ldg(rw + e * DDIM + k), acc[e]);
    }
#pragma unroll
    for (int e = 0; e < NEXP; e++)
#pragma unroll
        for (int off = 16; off; off >>= 1)
            acc[e] += __shfl_xor_sync(0xffffffffu, acc[e], off);
    if (lane == 0) {
        int best = 0;
        float bv = acc[0] + rb[0];
#pragma unroll
        for (int e = 1; e < NEXP; e++) {
            float v = acc[e] + rb[e];
            if (v > bv) { bv = v; best = e; }
        }
        int pos = atomicAdd(&g_cnt[best], 1);
        g_idx[best * N_TOK + pos] = gwarp;
    }
}

// ---------------------------------------------------------------------------
// Kernel 2: grouped gather-GEMM, mma.sync fp16 2-term split.
//   out = (A_hi * B_hi) [f32 acc]  +  (A_lo*1024 * B_hi) [f16 acc] / 1024
// Hypothesis test: f16-accumulator HMMA at double rate would cut MMA time 25%.
// Register-staged f32 loads -> in-register fp16 split -> smem tiles
// (double buffered, ONE __syncthreads per chunk).
// ---------------------------------------------------------------------------
__global__ __launch_bounds__(GT, 1)
void moe_gemm_mma(const float* __restrict__ x,
                  const float* __restrict__ ew,
                  const float* __restrict__ eb,
                  float* __restrict__ out) {
    const int e   = blockIdx.z;
    const int cnt = g_cnt[e];
    const int m0  = blockIdx.y * BM;
    if (m0 >= cnt) return;
    const int n0  = blockIdx.x * BN;

    extern __shared__ __align__(256) char smem[];
    int* srow = (int*)(smem + SM_SROW);
    const uint32_t sb = smem_u32(smem);
    const int tid  = threadIdx.x;
    const int lane = tid & 31;
    const int warp = tid >> 5;
    const int wm   = warp & 1;    // 64-row half (M)
    const int wn   = warp >> 1;   // 32-col quarter (N)

    if (tid < BM) {
        int r = m0 + tid;
        srow[tid] = g_idx[e * N_TOK + (r < cnt ? r : m0)];
    }
    __syncthreads();

    // ---- per-thread load plan: 8 float4 of A + 8 of B per chunk ----
    const float* wB = ew + ((size_t)e * DDIM + n0) * DDIM;
    uint32_t axoff[8], bxoff[8];
    const int prow  = tid >> 4;     // base row 0..15
    const int piece = tid & 15;     // float4 index within 64-col row
#pragma unroll
    for (int rep = 0; rep < 8; rep++) {
        int row = prow + rep * 16;                   // 0..127
        axoff[rep] = (uint32_t)(srow[row] * DDIM + piece * 4);
        bxoff[rep] = (uint32_t)(row * DDIM + piece * 4);
    }

    float4 ra[8], rb4[8];
    auto gload = [&](int t) {
        const uint32_t kg = (uint32_t)(t * BK);
#pragma unroll
        for (int rep = 0; rep < 8; rep++) {
            ra[rep]  = *(const float4*)(x  + axoff[rep] + kg);
            rb4[rep] = *(const float4*)(wB + bxoff[rep] + kg);
        }
    };
    auto convert_store = [&](int s) {
        const uint32_t bst = sb + SM_BF + (uint32_t)s * STAGEB;
#pragma unroll
        for (int rep = 0; rep < 8; rep++) {
            int row = prow + rep * 16;
            uint32_t bdst = bst + (uint32_t)(row * ROWB + piece * 8);
            uint32_t h0, l0, h1, l1;
            pack_split_f16(ra[rep].x, ra[rep].y, h0, l0);
            pack_split_f16(ra[rep].z, ra[rep].w, h1, l1);
            sts2(bdst + OFF_AHI, h0, h1);
            sts2(bdst + OFF_ALO, l0, l1);
            sts2(bdst + OFF_BHI,
                 pack_f16(rb4[rep].x, rb4[rep].y),
                 pack_f16(rb4[rep].z, rb4[rep].w));
        }
    };

    // ---- ldmatrix per-thread base offsets (within a tile) ----
    const uint32_t a_base =
        (uint32_t)((wm * 64 + (lane & 15)) * ROWB + ((lane >> 4) << 3) * 2);
    const uint32_t b_base =
        (uint32_t)((wn * 32 + (lane & 7) + ((lane >> 4) << 3)) * ROWB +
                   (((lane >> 3) & 1) << 3) * 2);

    float acc[4][4][4];          // f32 accumulators (hi term)
    uint32_t accl[4][4][2];      // f16x2 accumulators (lo term)
#pragma unroll
    for (int mi = 0; mi < 4; mi++)
#pragma unroll
        for (int nj = 0; nj < 4; nj++) {
#pragma unroll
            for (int q = 0; q < 4; q++) acc[mi][nj][q] = 0.f;
            accl[mi][nj][0] = 0u;
            accl[mi][nj][1] = 0u;
        }

    // Prologue: chunk 0 converted into buf 0; chunk 1 staged in regs.
    gload(0);
    convert_store(0);
    gload(1);
    __syncthreads();                  // buf0 ready for all warps

    for (int t = 0; t < NCHUNK; t++) {
        const int buf = t & 1;
        if (t + 1 < NCHUNK) convert_store(buf ^ 1);
        if (t + 2 < NCHUNK) gload(t + 2);

        const uint32_t bst = sb + SM_BF + (uint32_t)buf * STAGEB;
        const uint32_t ahw = bst + OFF_AHI + a_base;
        const uint32_t alw = bst + OFF_ALO + a_base;
        const uint32_t bhw = bst + OFF_BHI + b_base;
#pragma unroll
        for (int ks = 0; ks < BK / 16; ks++) {           // 4 k-steps
            const uint32_t ko = (uint32_t)(ks * 16 * 2); // 32 B per step
            uint32_t ah[4][4], al[4][4];
#pragma unroll
            for (int mi = 0; mi < 4; mi++) {
                ldsm4(ah[mi][0], ah[mi][1], ah[mi][2], ah[mi][3],
                      ahw + (uint32_t)(mi * 16 * ROWB) + ko);
                ldsm4(al[mi][0], al[mi][1], al[mi][2], al[mi][3],
                      alw + (uint32_t)(mi * 16 * ROWB) + ko);
            }
#pragma unroll
            for (int nj2 = 0; nj2 < 2; nj2++) {
                uint32_t bh0[2], bh1[2];
                ldsm4(bh0[0], bh0[1], bh1[0], bh1[1],
                      bhw + (uint32_t)(nj2 * 16 * ROWB) + ko);
                const int j0 = nj2 * 2, j1 = nj2 * 2 + 1;
                // hi term -> f32 accumulators
#pragma unroll
                for (int mi = 0; mi < 4; mi++) {
                    mma16816(acc[mi][j0], ah[mi], bh0);
                    mma16816(acc[mi][j1], ah[mi], bh1);
                }
                // lo term -> f16 accumulators (rate hypothesis under test)
#pragma unroll
                for (int mi = 0; mi < 4; mi++) {
                    mma16816_h(accl[mi][j0], al[mi], bh0);
                    mma16816_h(accl[mi][j1], al[mi], bh1);
                }
            }
        }
        __syncthreads();   // buf^1 fully written + buf fully read
    }

    // ---- Epilogue: combine hi + lo/1024 + bias, scatter store ----
    const float* ebp = eb + (size_t)e * DDIM + n0;
#pragma unroll
    for (int nj = 0; nj < 4; nj++) {
        const int col = wn * 32 + nj * 8 + (lane & 3) * 2;
        const float b0 = __ldg(ebp + col);
        const float b1 = __ldg(ebp + col + 1);
#pragma unroll
        for (int mi = 0; mi < 4; mi++) {
            const int r0 = wm * 64 + mi * 16 + (lane >> 2);
            const int r1 = r0 + 8;
            float2 lo01 = __half22float2(
                *reinterpret_cast<__half2*>(&accl[mi][nj][0]));
            float2 lo23 = __half22float2(
                *reinterpret_cast<__half2*>(&accl[mi][nj][1]));
            if (m0 + r0 < cnt) {
                float2 v = { acc[mi][nj][0] + lo01.x * LO_INV + b0,
                             acc[mi][nj][1] + lo01.y * LO_INV + b1 };
                *(float2*)(out + (size_t)srow[r0] * DDIM + n0 + col) = v;
            }
            if (m0 + r1 < cnt) {
                float2 v = { acc[mi][nj][2] + lo23.x * LO_INV + b0,
                             acc[mi][nj][3] + lo23.y * LO_INV + b1 };
                *(float2*)(out + (size_t)srow[r1] * DDIM + n0 + col) = v;
            }
        }
    }
}

// ---------------------------------------------------------------------------
// kernel_launch
// inputs: x[N,D] f32, router_w[E,D] f32, router_b[E] f32,
//         expert_w[E,D,D] f32, expert_b[E,D] f32 ; output f32 [N,D]
// ---------------------------------------------------------------------------
extern "C" void kernel_launch(void* const* d_in, const int* in_sizes, int n_in,
                              void* d_out, int out_size) {
    const float* x   = (const float*)d_in[0];
    const float* rw  = (const float*)d_in[1];
    const float* rb  = (const float*)d_in[2];
    const float* ew  = (const float*)d_in[3];
    const float* ebv = (const float*)d_in[4];
    float* out = (float*)d_out;

    cudaFuncSetAttribute(moe_gemm_mma,
                         cudaFuncAttributeMaxDynamicSharedMemorySize,
                         SMEM_TOTAL);

    zero_cnt_kernel<<<1, 32>>>();
    router_kernel<<<N_TOK / 8, 256>>>(x, rw, rb);

    dim3 grid(DDIM / BN, N_TOK / BM, NEXP);
    moe_gemm_mma<<<grid, GT, SMEM_TOTAL>>>(x, ew, ebv, out);
}

// round 16
// speedup vs baseline: 1.4393x; 1.4393x over previous
#include <cuda_runtime.h>
#include <cuda_fp16.h>
#include <cstdint>

#define N_TOK 16384
#define DDIM  1024
#define NEXP  8

#define BM 128
#define BN 128
#define BK 64
#define NCHUNK (DDIM / BK)       // 16
#define GT 256                   // 8 warps

// ---- shared memory layout ----
// fp16 tiles (double buffered): rows padded to 72 halves (144 B).
// 2 tiles per stage: A, B (single-term fp16 scheme).
#define ROWB   144
#define MATB   (BM * ROWB)                // 18432 B per matrix tile
#define STAGEB (2 * MATB)                 // 36864 B per stage
#define OFF_A  0
#define OFF_B  (1 * MATB)
#define SM_SROW 0
#define SM_BF   512
#define SMEM_TOTAL (SM_BF + 2 * STAGEB)   // 74240 B

// ---------------------------------------------------------------------------
// Device scratch: ONLY the small routing tables.
// ---------------------------------------------------------------------------
__device__ int g_cnt[NEXP];
__device__ int g_idx[NEXP * N_TOK];

// ---------------------------------------------------------------------------
// PTX helpers (sm_80-level only)
// ---------------------------------------------------------------------------
__device__ __forceinline__ uint32_t smem_u32(const void* p) {
    uint32_t a;
    asm("{ .reg .u64 t; cvta.to.shared.u64 t, %1; cvt.u32.u64 %0, t; }"
        : "=r"(a) : "l"(p));
    return a;
}
__device__ __forceinline__ void ldsm4(uint32_t& r0, uint32_t& r1,
                                      uint32_t& r2, uint32_t& r3, uint32_t a) {
    asm volatile("ldmatrix.sync.aligned.m8n8.x4.shared.b16 {%0,%1,%2,%3}, [%4];"
                 : "=r"(r0), "=r"(r1), "=r"(r2), "=r"(r3) : "r"(a));
}
// fp16 MMA, f32 accumulate. Non-volatile: pure register dataflow.
__device__ __forceinline__ void mma16816(float* d, const uint32_t* a,
                                         const uint32_t* b) {
    asm("mma.sync.aligned.m16n8k16.row.col.f32.f16.f16.f32 "
        "{%0,%1,%2,%3}, {%4,%5,%6,%7}, {%8,%9}, {%0,%1,%2,%3};"
        : "+f"(d[0]), "+f"(d[1]), "+f"(d[2]), "+f"(d[3])
        : "r"(a[0]), "r"(a[1]), "r"(a[2]), "r"(a[3]),
          "r"(b[0]), "r"(b[1]));
}
__device__ __forceinline__ uint32_t pack_f16(float f0, float f1) {
    __half2 h = __floats2half2_rn(f0, f1);
    return *reinterpret_cast<uint32_t*>(&h);
}
__device__ __forceinline__ void sts2(uint32_t a, uint32_t v0, uint32_t v1) {
    asm volatile("st.shared.v2.u32 [%0], {%1,%2};" :: "r"(a), "r"(v0), "r"(v1));
}

// ---------------------------------------------------------------------------
// Kernel 0: zero per-expert counters (graph replays need this every launch).
// ---------------------------------------------------------------------------
__global__ void zero_cnt_kernel() {
    if (threadIdx.x < NEXP) g_cnt[threadIdx.x] = 0;
}

// ---------------------------------------------------------------------------
// Kernel 1: router. One warp/token; argmax, first-index tie-break.
// ---------------------------------------------------------------------------
__global__ void router_kernel(const float* __restrict__ x,
                              const float* __restrict__ rw,
                              const float* __restrict__ rb) {
    int gwarp = (int)((blockIdx.x * blockDim.x + threadIdx.x) >> 5);
    int lane  = threadIdx.x & 31;
    if (gwarp >= N_TOK) return;
    const float* xr = x + (size_t)gwarp * DDIM;
    float acc[NEXP];
#pragma unroll
    for (int e = 0; e < NEXP; e++) acc[e] = 0.f;
    for (int k = lane; k < DDIM; k += 32) {
        float xv = __ldg(xr + k);
#pragma unroll
        for (int e = 0; e < NEXP; e++)
            acc[e] = fmaf(xv, __ldg(rw + e * DDIM + k), acc[e]);
    }
#pragma unroll
    for (int e = 0; e < NEXP; e++)
#pragma unroll
        for (int off = 16; off; off >>= 1)
            acc[e] += __shfl_xor_sync(0xffffffffu, acc[e], off);
    if (lane == 0) {
        int best = 0;
        float bv = acc[0] + rb[0];
#pragma unroll
        for (int e = 1; e < NEXP; e++) {
            float v = acc[e] + rb[e];
            if (v > bv) { bv = v; best = e; }
        }
        int pos = atomicAdd(&g_cnt[best], 1);
        g_idx[best * N_TOK + pos] = gwarp;
    }
}

// ---------------------------------------------------------------------------
// Kernel 2: grouped gather-GEMM, mma.sync fp16 single-term, f32 accum.
//   out[tok, n] = sum_k f16(x[tok,k]) * f16(ew[e,n,k]) + eb[e,n]
//   (f16 RN of both operands; fp32 accumulation. L2 rel err ~4e-4.)
// Register-staged f32 loads -> in-register f16 convert -> smem tiles
// (double buffered, ONE __syncthreads per chunk). Per chunk: 4 k-steps x
// (6 ldmatrix.x4 + 16 HMMA).
// ---------------------------------------------------------------------------
__global__ __launch_bounds__(GT, 1)
void moe_gemm_mma(const float* __restrict__ x,
                  const float* __restrict__ ew,
                  const float* __restrict__ eb,
                  float* __restrict__ out) {
    const int e   = blockIdx.z;
    const int cnt = g_cnt[e];
    const int m0  = blockIdx.y * BM;
    if (m0 >= cnt) return;
    const int n0  = blockIdx.x * BN;

    extern __shared__ __align__(256) char smem[];
    int* srow = (int*)(smem + SM_SROW);
    const uint32_t sb = smem_u32(smem);
    const int tid  = threadIdx.x;
    const int lane = tid & 31;
    const int warp = tid >> 5;
    const int wm   = warp & 1;    // 64-row half (M)
    const int wn   = warp >> 1;   // 32-col quarter (N)

    if (tid < BM) {
        int r = m0 + tid;
        srow[tid] = g_idx[e * N_TOK + (r < cnt ? r : m0)];
    }
    __syncthreads();

    // ---- per-thread load plan: 8 float4 of A + 8 of B per chunk ----
    const float* wB = ew + ((size_t)e * DDIM + n0) * DDIM;
    uint32_t axoff[8], bxoff[8];
    const int prow  = tid >> 4;     // base row 0..15
    const int piece = tid & 15;     // float4 index within 64-col row
#pragma unroll
    for (int rep = 0; rep < 8; rep++) {
        int row = prow + rep * 16;                   // 0..127
        axoff[rep] = (uint32_t)(srow[row] * DDIM + piece * 4);
        bxoff[rep] = (uint32_t)(row * DDIM + piece * 4);
    }

    float4 ra[8], rb4[8];
    auto gload = [&](int t) {
        const uint32_t kg = (uint32_t)(t * BK);
#pragma unroll
        for (int rep = 0; rep < 8; rep++) {
            ra[rep]  = *(const float4*)(x  + axoff[rep] + kg);
            rb4[rep] = *(const float4*)(wB + bxoff[rep] + kg);
        }
    };
    auto convert_store = [&](int s) {
        const uint32_t bst = sb + SM_BF + (uint32_t)s * STAGEB;
#pragma unroll
        for (int rep = 0; rep < 8; rep++) {
            int row = prow + rep * 16;
            uint32_t bdst = bst + (uint32_t)(row * ROWB + piece * 8);
            sts2(bdst + OFF_A,
                 pack_f16(ra[rep].x, ra[rep].y),
                 pack_f16(ra[rep].z, ra[rep].w));
            sts2(bdst + OFF_B,
                 pack_f16(rb4[rep].x, rb4[rep].y),
                 pack_f16(rb4[rep].z, rb4[rep].w));
        }
    };

    // ---- ldmatrix per-thread base offsets (within a tile) ----
    const uint32_t a_base =
        (uint32_t)((wm * 64 + (lane & 15)) * ROWB + ((lane >> 4) << 3) * 2);
    const uint32_t b_base =
        (uint32_t)((wn * 32 + (lane & 7) + ((lane >> 4) << 3)) * ROWB +
                   (((lane >> 3) & 1) << 3) * 2);

    float acc[4][4][4];
#pragma unroll
    for (int mi = 0; mi < 4; mi++)
#pragma unroll
        for (int nj = 0; nj < 4; nj++)
#pragma unroll
            for (int q = 0; q < 4; q++) acc[mi][nj][q] = 0.f;

    // Prologue: chunk 0 converted into buf 0; chunk 1 staged in regs.
    gload(0);
    convert_store(0);
    gload(1);
    __syncthreads();                  // buf0 ready for all warps

    for (int t = 0; t < NCHUNK; t++) {
        const int buf = t & 1;
        if (t + 1 < NCHUNK) convert_store(buf ^ 1);
        if (t + 2 < NCHUNK) gload(t + 2);

        const uint32_t bst = sb + SM_BF + (uint32_t)buf * STAGEB;
        const uint32_t ahw = bst + OFF_A + a_base;
        const uint32_t bhw = bst + OFF_B + b_base;
#pragma unroll
        for (int ks = 0; ks < BK / 16; ks++) {           // 4 k-steps
            const uint32_t ko = (uint32_t)(ks * 16 * 2); // 32 B per step
            uint32_t ah[4][4];
#pragma unroll
            for (int mi = 0; mi < 4; mi++)
                ldsm4(ah[mi][0], ah[mi][1], ah[mi][2], ah[mi][3],
                      ahw + (uint32_t)(mi * 16 * ROWB) + ko);
#pragma unroll
            for (int nj2 = 0; nj2 < 2; nj2++) {
                uint32_t bh0[2], bh1[2];
                ldsm4(bh0[0], bh0[1], bh1[0], bh1[1],
                      bhw + (uint32_t)(nj2 * 16 * ROWB) + ko);
                const int j0 = nj2 * 2, j1 = nj2 * 2 + 1;
#pragma unroll
                for (int mi = 0; mi < 4; mi++) {
                    mma16816(acc[mi][j0], ah[mi], bh0);
                    mma16816(acc[mi][j1], ah[mi], bh1);
                }
            }
        }
        __syncthreads();   // buf^1 fully written + buf fully read
    }

    // ---- Epilogue: bias add + scatter store ----
    const float* ebp = eb + (size_t)e * DDIM + n0;
#pragma unroll
    for (int nj = 0; nj < 4; nj++) {
        const int col = wn * 32 + nj * 8 + (lane & 3) * 2;
        const float b0 = __ldg(ebp + col);
        const float b1 = __ldg(ebp + col + 1);
#pragma unroll
        for (int mi = 0; mi < 4; mi++) {
            const int r0 = wm * 64 + mi * 16 + (lane >> 2);
            const int r1 = r0 + 8;
            if (m0 + r0 < cnt) {
                float2 v = { acc[mi][nj][0] + b0, acc[mi][nj][1] + b1 };
                *(float2*)(out + (size_t)srow[r0] * DDIM + n0 + col) = v;
            }
            if (m0 + r1 < cnt) {
                float2 v = { acc[mi][nj][2] + b0, acc[mi][nj][3] + b1 };
                *(float2*)(out + (size_t)srow[r1] * DDIM + n0 + col) = v;
            }
        }
    }
}

// ---------------------------------------------------------------------------
// kernel_launch
// inputs: x[N,D] f32, router_w[E,D] f32, router_b[E] f32,
//         expert_w[E,D,D] f32, expert_b[E,D] f32 ; output f32 [N,D]
// ---------------------------------------------------------------------------
extern "C" void kernel_launch(void* const* d_in, const int* in_sizes, int n_in,
                              void* d_out, int out_size) {
    const float* x   = (const float*)d_in[0];
    const float* rw  = (const float*)d_in[1];
    const float* rb  = (const float*)d_in[2];
    const float* ew  = (const float*)d_in[3];
    const float* ebv = (const float*)d_in[4];
    float* out = (float*)d_out;

    cudaFuncSetAttribute(moe_gemm_mma,
                         cudaFuncAttributeMaxDynamicSharedMemorySize,
                         SMEM_TOTAL);

    zero_cnt_kernel<<<1, 32>>>();
    router_kernel<<<N_TOK / 8, 256>>>(x, rw, rb);

    dim3 grid(DDIM / BN, N_TOK / BM, NEXP);
    moe_gemm_mma<<<grid, GT, SMEM_TOTAL>>>(x, ew, ebv, out);
}

// round 17
// speedup vs baseline: 1.6889x; 1.1734x over previous
#include <cuda_runtime.h>
#include <cuda_fp16.h>
#include <cstdint>

#define N_TOK 16384
#define DDIM  1024
#define NEXP  8

#define BM 128
#define BN 128
#define BK 64
#define NCHUNK (DDIM / BK)       // 16
#define NSTAGE 3
#define GT 256                   // 8 warps

// ---- shared memory layout ----
// fp16 tiles, 3-stage ring: rows padded to 72 halves (144 B).
#define ROWB   144
#define MATB   (BM * ROWB)                // 18432 B per matrix tile
#define STAGEB (2 * MATB)                 // A + B = 36864 B per stage
#define OFF_A  0
#define OFF_B  (1 * MATB)
#define SM_SROW 0
#define SM_BF   512
#define SMEM_TOTAL (SM_BF + NSTAGE * STAGEB)   // 111104 B

// ---------------------------------------------------------------------------
// Device scratch: routing tables + f16 copies of x and expert weights.
// ---------------------------------------------------------------------------
__device__ int g_cnt[NEXP];
__device__ int g_idx[NEXP * N_TOK];
__device__ __align__(16) __half g_x16[(size_t)N_TOK * DDIM];          // 32 MB
__device__ __align__(16) __half g_w16[(size_t)NEXP * DDIM * DDIM];    // 16 MB

// ---------------------------------------------------------------------------
// PTX helpers (sm_80-level only)
// ---------------------------------------------------------------------------
__device__ __forceinline__ uint32_t smem_u32(const void* p) {
    uint32_t a;
    asm("{ .reg .u64 t; cvta.to.shared.u64 t, %1; cvt.u32.u64 %0, t; }"
        : "=r"(a) : "l"(p));
    return a;
}
__device__ __forceinline__ void cp16(uint32_t dst, const void* src) {
    asm volatile("cp.async.cg.shared.global [%0], [%1], 16;"
                 :: "r"(dst), "l"(src) : "memory");
}
#define CP_COMMIT() asm volatile("cp.async.commit_group;" ::: "memory")
template <int N>
__device__ __forceinline__ void cp_wait() {
    asm volatile("cp.async.wait_group %0;" :: "n"(N) : "memory");
}
__device__ __forceinline__ void ldsm4(uint32_t& r0, uint32_t& r1,
                                      uint32_t& r2, uint32_t& r3, uint32_t a) {
    asm volatile("ldmatrix.sync.aligned.m8n8.x4.shared.b16 {%0,%1,%2,%3}, [%4];"
                 : "=r"(r0), "=r"(r1), "=r"(r2), "=r"(r3) : "r"(a));
}
// fp16 MMA, f32 accumulate. Non-volatile: pure register dataflow.
__device__ __forceinline__ void mma16816(float* d, const uint32_t* a,
                                         const uint32_t* b) {
    asm("mma.sync.aligned.m16n8k16.row.col.f32.f16.f16.f32 "
        "{%0,%1,%2,%3}, {%4,%5,%6,%7}, {%8,%9}, {%0,%1,%2,%3};"
        : "+f"(d[0]), "+f"(d[1]), "+f"(d[2]), "+f"(d[3])
        : "r"(a[0]), "r"(a[1]), "r"(a[2]), "r"(a[3]),
          "r"(b[0]), "r"(b[1]));
}
__device__ __forceinline__ uint32_t pack_f16(float f0, float f1) {
    __half2 h = __floats2half2_rn(f0, f1);
    return *reinterpret_cast<uint32_t*>(&h);
}

// ---------------------------------------------------------------------------
// Kernel 0: zero per-expert counters (graph replays need this every launch).
// ---------------------------------------------------------------------------
__global__ void zero_cnt_kernel() {
    if (threadIdx.x < NEXP) g_cnt[threadIdx.x] = 0;
}

// ---------------------------------------------------------------------------
// Kernel 1: router (+ fused x -> f16 conversion; router already reads x).
// One warp/token; argmax, first-index tie-break.
// ---------------------------------------------------------------------------
__global__ void router_kernel(const float* __restrict__ x,
                              const float* __restrict__ rw,
                              const float* __restrict__ rb) {
    int gwarp = (int)((blockIdx.x * blockDim.x + threadIdx.x) >> 5);
    int lane  = threadIdx.x & 31;
    if (gwarp >= N_TOK) return;
    const float* xr = x + (size_t)gwarp * DDIM;
    __half* xo = g_x16 + (size_t)gwarp * DDIM;
    float acc[NEXP];
#pragma unroll
    for (int e = 0; e < NEXP; e++) acc[e] = 0.f;
    for (int k = lane; k < DDIM; k += 32) {
        float xv = __ldg(xr + k);
        xo[k] = __float2half_rn(xv);
#pragma unroll
        for (int e = 0; e < NEXP; e++)
            acc[e] = fmaf(xv, __ldg(rw + e * DDIM + k), acc[e]);
    }
#pragma unroll
    for (int e = 0; e < NEXP; e++)
#pragma unroll
        for (int off = 16; off; off >>= 1)
            acc[e] += __shfl_xor_sync(0xffffffffu, acc[e], off);
    if (lane == 0) {
        int best = 0;
        float bv = acc[0] + rb[0];
#pragma unroll
        for (int e = 1; e < NEXP; e++) {
            float v = acc[e] + rb[e];
            if (v > bv) { bv = v; best = e; }
        }
        int pos = atomicAdd(&g_cnt[best], 1);
        g_idx[best * N_TOK + pos] = gwarp;
    }
}

// ---------------------------------------------------------------------------
// Kernel 1b: expert weights -> f16 (one pass; removes per-m-tile reconvert).
// ---------------------------------------------------------------------------
__global__ void convert_w_kernel(const float* __restrict__ w) {
    size_t total4 = (size_t)NEXP * DDIM * DDIM / 4;
    size_t stride = (size_t)gridDim.x * blockDim.x;
    for (size_t i = (size_t)blockIdx.x * blockDim.x + threadIdx.x;
         i < total4; i += stride) {
        float4 v = ((const float4*)w)[i];
        uint2 o = { pack_f16(v.x, v.y), pack_f16(v.z, v.w) };
        ((uint2*)g_w16)[i] = o;
    }
}

// ---------------------------------------------------------------------------
// Kernel 2: grouped gather-GEMM, mma.sync fp16 single-term, f32 accum.
//   out[tok, n] = sum_k f16(x[tok,k]) * f16(ew[e,n,k]) + eb[e,n]
// f16 operands preconverted in global; cp.async 3-stage ring; loads for
// chunk t+2 issued AFTER the barrier of iteration t (stage (t+2)%3 was
// last read before that barrier -> race-free). ONE barrier per chunk.
// Per chunk: 4 k-steps x (6 ldmatrix.x4 + 16 HMMA).
// ---------------------------------------------------------------------------
__global__ __launch_bounds__(GT, 2)
void moe_gemm_mma(const float* __restrict__ eb, float* __restrict__ out) {
    const int e   = blockIdx.z;
    const int cnt = g_cnt[e];
    const int m0  = blockIdx.y * BM;
    if (m0 >= cnt) return;
    const int n0  = blockIdx.x * BN;

    extern __shared__ __align__(256) char smem[];
    int* srow = (int*)(smem + SM_SROW);
    const uint32_t sb = smem_u32(smem);
    const int tid  = threadIdx.x;
    const int lane = tid & 31;
    const int warp = tid >> 5;
    const int wm   = warp & 1;    // 64-row half (M)
    const int wn   = warp >> 1;   // 32-col quarter (N)

    if (tid < BM) {
        int r = m0 + tid;
        srow[tid] = g_idx[e * N_TOK + (r < cnt ? r : m0)];
    }
    __syncthreads();

    // ---- cp.async plan: 4 x 16B of A + 4 x 16B of B per thread per chunk --
    const __half* wB = g_w16 + ((size_t)e * DDIM + n0) * DDIM;
    size_t aoff[4], boff[4];
    uint32_t doff[4];
    const int prow  = tid >> 3;     // base row 0..31
    const int piece = tid & 7;      // 16B piece (8 halves) within 64-half row
#pragma unroll
    for (int rep = 0; rep < 4; rep++) {
        int row = prow + rep * 32;                   // 0..127
        aoff[rep] = (size_t)srow[row] * DDIM + piece * 8;
        boff[rep] = (size_t)row * DDIM + piece * 8;
        doff[rep] = (uint32_t)(row * ROWB + piece * 16);
    }
    auto load_chunk = [&](int t, int s) {
        const size_t kg = (size_t)t * BK;
        const uint32_t st = sb + SM_BF + (uint32_t)s * STAGEB;
#pragma unroll
        for (int rep = 0; rep < 4; rep++) {
            cp16(st + OFF_A + doff[rep], g_x16 + aoff[rep] + kg);
            cp16(st + OFF_B + doff[rep], wB    + boff[rep] + kg);
        }
    };

    // ---- ldmatrix per-thread base offsets (within a tile) ----
    const uint32_t a_base =
        (uint32_t)((wm * 64 + (lane & 15)) * ROWB + ((lane >> 4) << 3) * 2);
    const uint32_t b_base =
        (uint32_t)((wn * 32 + (lane & 7) + ((lane >> 4) << 3)) * ROWB +
                   (((lane >> 3) & 1) << 3) * 2);

    float acc[4][4][4];
#pragma unroll
    for (int mi = 0; mi < 4; mi++)
#pragma unroll
        for (int nj = 0; nj < 4; nj++)
#pragma unroll
            for (int q = 0; q < 4; q++) acc[mi][nj][q] = 0.f;

    // Prologue: chunks 0,1 into stages 0,1 (two cp groups in flight).
    load_chunk(0, 0); CP_COMMIT();
    load_chunk(1, 1); CP_COMMIT();

    for (int t = 0; t < NCHUNK; t++) {
        const int s = t % NSTAGE;
        // Drain so chunk t is resident (tail: drain everything).
        if (t + 1 < NCHUNK) cp_wait<1>(); else cp_wait<0>();
        __syncthreads();
        // Safe to overwrite stage (t+2)%3 now (last read before this barrier).
        if (t + 2 < NCHUNK) {
            int ns = s + 2; if (ns >= NSTAGE) ns -= NSTAGE;
            load_chunk(t + 2, ns);
            CP_COMMIT();
        }

        const uint32_t st  = sb + SM_BF + (uint32_t)s * STAGEB;
        const uint32_t ahw = st + OFF_A + a_base;
        const uint32_t bhw = st + OFF_B + b_base;
#pragma unroll
        for (int ks = 0; ks < BK / 16; ks++) {           // 4 k-steps
            const uint32_t ko = (uint32_t)(ks * 16 * 2); // 32 B per step
            uint32_t ah[4][4];
#pragma unroll
            for (int mi = 0; mi < 4; mi++)
                ldsm4(ah[mi][0], ah[mi][1], ah[mi][2], ah[mi][3],
                      ahw + (uint32_t)(mi * 16 * ROWB) + ko);
#pragma unroll
            for (int nj2 = 0; nj2 < 2; nj2++) {
                uint32_t bh0[2], bh1[2];
                ldsm4(bh0[0], bh0[1], bh1[0], bh1[1],
                      bhw + (uint32_t)(nj2 * 16 * ROWB) + ko);
                const int j0 = nj2 * 2, j1 = nj2 * 2 + 1;
#pragma unroll
                for (int mi = 0; mi < 4; mi++) {
                    mma16816(acc[mi][j0], ah[mi], bh0);
                    mma16816(acc[mi][j1], ah[mi], bh1);
                }
            }
        }
    }

    // ---- Epilogue: bias add + scatter store ----
    const float* ebp = eb + (size_t)e * DDIM + n0;
#pragma unroll
    for (int nj = 0; nj < 4; nj++) {
        const int col = wn * 32 + nj * 8 + (lane & 3) * 2;
        const float b0 = __ldg(ebp + col);
        const float b1 = __ldg(ebp + col + 1);
#pragma unroll
        for (int mi = 0; mi < 4; mi++) {
            const int r0 = wm * 64 + mi * 16 + (lane >> 2);
            const int r1 = r0 + 8;
            if (m0 + r0 < cnt) {
                float2 v = { acc[mi][nj][0] + b0, acc[mi][nj][1] + b1 };
                *(float2*)(out + (size_t)srow[r0] * DDIM + n0 + col) = v;
            }
            if (m0 + r1 < cnt) {
                float2 v = { acc[mi][nj][2] + b0, acc[mi][nj][3] + b1 };
                *(float2*)(out + (size_t)srow[r1] * DDIM + n0 + col) = v;
            }
        }
    }
}

// ---------------------------------------------------------------------------
// kernel_launch
// inputs: x[N,D] f32, router_w[E,D] f32, router_b[E] f32,
//         expert_w[E,D,D] f32, expert_b[E,D] f32 ; output f32 [N,D]
// ---------------------------------------------------------------------------
extern "C" void kernel_launch(void* const* d_in, const int* in_sizes, int n_in,
                              void* d_out, int out_size) {
    const float* x   = (const float*)d_in[0];
    const float* rw  = (const float*)d_in[1];
    const float* rb  = (const float*)d_in[2];
    const float* ew  = (const float*)d_in[3];
    const float* ebv = (const float*)d_in[4];
    float* out = (float*)d_out;

    cudaFuncSetAttribute(moe_gemm_mma,
                         cudaFuncAttributeMaxDynamicSharedMemorySize,
                         SMEM_TOTAL);

    zero_cnt_kernel<<<1, 32>>>();
    router_kernel<<<N_TOK / 8, 256>>>(x, rw, rb);
    convert_w_kernel<<<2048, 256>>>(ew);

    dim3 grid(DDIM / BN, N_TOK / BM, NEXP);
    moe_gemm_mma<<<grid, GT, SMEM_TOTAL>>>(ebv, out);
}